// round 6
// baseline (speedup 1.0000x reference)
#include <cuda_runtime.h>
#include <cuda_bf16.h>
#include <stdint.h>

// ---------------------------------------------------------------------------
// VectorQuantizer on GB300 — exact fp32 FFMA2 distance GEMM.
//   z      : [64, 256, 32, 32] f32   (d_in[0])
//   emb_w  : [1024, 256]       f32   (d_in[1])
//   out    : z_q [64,256,32,32] f32, then loss scalar (last element)
//
// d = fl( fl(z_sq + e_sq[k]) - 2*dot_k ), fp32; ties -> lowest code index.
// f32x2 packs ROW pairs (z side); e values are pre-duplicated at pack time
// so the inner loop is pure {LDS.128, FFMA2}. cp.async double-buffering
// hides all staging latency.
// ---------------------------------------------------------------------------

#define CDIM   256
#define NROWS  65536
#define KCODES 1024

__device__ float g_esq[KCODES];
__device__ float g_zsq[NROWS];
__device__ int   g_idx[NROWS];
__device__ float g_partials[2048];
// 64 tiles (kt*8+c0) of 8192 floats: [cc 0..31][chunk 0..63][q 0..1][dup 0..1]
// chunk holds codes 2*chunk, 2*chunk+1 (each duplicated) for column c0*32+cc.
__device__ float g_epack[64 * 8192];   // 2 MB

// ---------------------------------------------------------------------------
__device__ __forceinline__ unsigned long long ffma2(unsigned long long a,
                                                    unsigned long long b,
                                                    unsigned long long c) {
    unsigned long long d;
    asm("fma.rn.f32x2 %0, %1, %2, %3;" : "=l"(d) : "l"(a), "l"(b), "l"(c));
    return d;
}
__device__ __forceinline__ void unpack2(unsigned long long v, float& lo, float& hi) {
    asm("mov.b64 {%0, %1}, %2;" : "=f"(lo), "=f"(hi) : "l"(v));
}
__device__ __forceinline__ uint32_t smem_u32(const void* p) {
    uint32_t a;
    asm("{ .reg .u64 t; cvta.to.shared.u64 t, %1; cvt.u32.u64 %0, t; }"
        : "=r"(a) : "l"(p));
    return a;
}
__device__ __forceinline__ void cp16(uint32_t dst, const void* src) {
    asm volatile("cp.async.cg.shared.global [%0], [%1], 16;"
                 :: "r"(dst), "l"(src));
}
#define CP_COMMIT() asm volatile("cp.async.commit_group;" ::: "memory")
#define CP_WAIT1()  asm volatile("cp.async.wait_group 1;" ::: "memory")

// ---------------------------------------------------------------------------
// K0: pack emb into duplicated, chunk-interleaved tiles
// ---------------------------------------------------------------------------
__global__ void k_epack(const float* __restrict__ emb) {
    int idx = blockIdx.x * 256 + threadIdx.x;      // 262144 = 1024*256
    int k = idx >> 8, c = idx & 255;
    int kt = k >> 7, r = k & 127, chunk = r >> 1, q = r & 1;
    int c0 = c >> 5, cc = c & 31;
    float v = emb[k * CDIM + c];
    float* dst = g_epack + ((size_t)(kt * 8 + c0)) * 8192
                         + cc * 256 + chunk * 4 + q * 2;
    dst[0] = v;
    dst[1] = v;
}

// ---------------------------------------------------------------------------
// K1: norms
// ---------------------------------------------------------------------------
__global__ void k_esq(const float* __restrict__ emb) {
    int w = (blockIdx.x * blockDim.x + threadIdx.x) >> 5, lane = threadIdx.x & 31;
    if (w >= KCODES) return;
    const float* row = emb + (size_t)w * CDIM;
    float s = 0.f;
#pragma unroll
    for (int i = lane; i < CDIM; i += 32) { float v = row[i]; s = fmaf(v, v, s); }
#pragma unroll
    for (int o = 16; o; o >>= 1) s += __shfl_xor_sync(0xffffffffu, s, o);
    if (!lane) g_esq[w] = s;
}
__global__ void k_zsq(const float* __restrict__ z) {
    int n = blockIdx.x * 256 + threadIdx.x;
    int b = n >> 10, hw = n & 1023;
    const float* p = z + (((size_t)b * CDIM) << 10) + hw;
    float s = 0.f;
#pragma unroll 8
    for (int c = 0; c < CDIM; c++) { float v = p[(size_t)c << 10]; s = fmaf(v, v, s); }
    g_zsq[n] = s;
}

// ---------------------------------------------------------------------------
// K2: fused distance GEMM + argmin.
//   block: 128 rows x 1024 codes; 64 flat steps (kt 0..7 x c0 0..7).
//   thread (tx=t&15, ty=t>>4): rows ty*8+0..7 as 4 f32x2 row-pairs,
//   8 codes = chunks {tx, 16+tx, 32+tx, 48+tx} x {q=0,1}.
//   acc[p][s*2+q]: halves = dots of rows (2p, 2p+1) vs code (s*16+tx)*2+q.
// dynamic smem (floats): zb[2][4096], eb[2][8192], esq[1024], zsq[128];
// reduction reuses zb after a barrier.
// ---------------------------------------------------------------------------
#define F_ZB0 0
#define F_ZB1 4096
#define F_EB0 8192
#define F_EB1 16384
#define F_ESQ 24576
#define F_ZSQ 25600
#define F_TOT 25728            // 102912 bytes

__global__ void __launch_bounds__(256, 2)
k_dist_argmin(const float* __restrict__ z) {
    extern __shared__ __align__(16) float sm[];
    const uint32_t sb = smem_u32(sm);

    const int t    = threadIdx.x;
    const int tx   = t & 15;
    const int ty   = t >> 4;
    const int row0 = blockIdx.x * 128;
    const int bb   = row0 >> 10;
    const int hw0  = row0 & 1023;

    for (int i = t; i < KCODES; i += 256) sm[F_ESQ + i] = g_esq[i];
    if (t < 128) sm[F_ZSQ + t] = g_zsq[row0 + t];

    // staging: step s -> kt = s>>3, c0 = s&7, e-tile index = s.
    // z: 1024 16B-chunks (4/thread), id = t + 256*j: cr = id>>5, co = id&31.
    // e: 2048 16B-chunks (8/thread), linear copy of g_epack tile.
    const float* zsrc0 = z + (((size_t)bb * CDIM) << 10) + hw0;

    auto stage = [&](int s, int par) {
        const int c0 = s & 7;
        uint32_t zdst = sb + (par ? F_ZB1 : F_ZB0) * 4;
        uint32_t edst = sb + (par ? F_EB1 : F_EB0) * 4;
        const float* zs = zsrc0 + (((size_t)(c0 * 32)) << 10);
#pragma unroll
        for (int j = 0; j < 4; j++) {
            int id = t + 256 * j;
            int cr = id >> 5, co = (id & 31) * 4;
            cp16(zdst + (uint32_t)(cr * 128 + co) * 4,
                 zs + (((size_t)cr) << 10) + co);
        }
        const float* es = g_epack + ((size_t)s) * 8192 + t * 4;
#pragma unroll
        for (int j = 0; j < 8; j++)
            cp16(edst + (uint32_t)(t + 256 * j) * 16, es + j * 1024);
    };

    float bestD[8];
    int   bestI[8];
#pragma unroll
    for (int i = 0; i < 8; ++i) { bestD[i] = __int_as_float(0x7f800000); bestI[i] = 0; }

    unsigned long long acc[4][8];

    stage(0, 0);
    CP_COMMIT();

    for (int s = 0; s < 64; s++) {
        const int par = s & 1;
        __syncthreads();                    // buf[(s+1)&1] readers (step s-1) done
        if (s < 63) stage(s + 1, par ^ 1);
        CP_COMMIT();
        CP_WAIT1();                         // step s's copies complete
        __syncthreads();

        if ((s & 7) == 0) {
#pragma unroll
            for (int p = 0; p < 4; ++p)
#pragma unroll
                for (int j = 0; j < 8; ++j) acc[p][j] = 0ull;
        }

        const float* zb = sm + (par ? F_ZB1 : F_ZB0);
        const float* eb = sm + (par ? F_EB1 : F_EB0);

#pragma unroll 2
        for (int cc = 0; cc < 32; cc++) {
            ulonglong2 zp = *reinterpret_cast<const ulonglong2*>(
                &zb[cc * 128 + ty * 8]);
            ulonglong2 zq = *reinterpret_cast<const ulonglong2*>(
                &zb[cc * 128 + ty * 8 + 4]);
            unsigned long long zr[4] = { zp.x, zp.y, zq.x, zq.y };
#pragma unroll
            for (int sc = 0; sc < 4; sc++) {
                ulonglong2 ep = *reinterpret_cast<const ulonglong2*>(
                    &eb[cc * 256 + (sc * 16 + tx) * 4]);
#pragma unroll
                for (int p = 0; p < 4; p++) {
                    acc[p][sc * 2 + 0] = ffma2(zr[p], ep.x, acc[p][sc * 2 + 0]);
                    acc[p][sc * 2 + 1] = ffma2(zr[p], ep.y, acc[p][sc * 2 + 1]);
                }
            }
        }

        if ((s & 7) == 7) {
            // kt epilogue: codes ascend over (sc, q); strict < = first-min
            const int kb = (s >> 3) * 128;
#pragma unroll
            for (int p = 0; p < 4; p++) {
                float zq0 = sm[F_ZSQ + ty * 8 + 2 * p];
                float zq1 = sm[F_ZSQ + ty * 8 + 2 * p + 1];
#pragma unroll
                for (int sc = 0; sc < 4; sc++) {
#pragma unroll
                    for (int q = 0; q < 2; q++) {
                        int   k = kb + (sc * 16 + tx) * 2 + q;
                        float esq = sm[F_ESQ + k];
                        float lo, hi;
                        unpack2(acc[p][sc * 2 + q], lo, hi);
                        float d0 = fmaf(-2.0f, lo, zq0 + esq);
                        if (d0 < bestD[2 * p]) { bestD[2 * p] = d0; bestI[2 * p] = k; }
                        float d1 = fmaf(-2.0f, hi, zq1 + esq);
                        if (d1 < bestD[2 * p + 1]) { bestD[2 * p + 1] = d1; bestI[2 * p + 1] = k; }
                    }
                }
            }
        }
    }

    // cross-thread (tx) reduction per row, lowest-index tie-break
    __syncthreads();
    float* rd = sm + F_ZB0;                 // [128][16]
    int*   ri = (int*)(sm + F_ZB0 + 2048);  // [128][16]
#pragma unroll
    for (int i = 0; i < 8; ++i) {
        rd[(ty * 8 + i) * 16 + tx] = bestD[i];
        ri[(ty * 8 + i) * 16 + tx] = bestI[i];
    }
    __syncthreads();
    if (t < 128) {
        float bd = rd[t * 16];
        int   bi = ri[t * 16];
#pragma unroll
        for (int x = 1; x < 16; ++x) {
            float dd = rd[t * 16 + x];
            int   ii = ri[t * 16 + x];
            if (dd < bd || (dd == bd && ii < bi)) { bd = dd; bi = ii; }
        }
        g_idx[row0 + t] = bi;
    }
}

// ---------------------------------------------------------------------------
// K3: gather z_q -> out ([B,C,H,W]), per-block loss partials
// ---------------------------------------------------------------------------
__global__ void __launch_bounds__(256)
k_output(const float* __restrict__ z, const float* __restrict__ emb,
         float* __restrict__ out) {
    __shared__ float es[32][257];
    __shared__ int   sid[32];
    __shared__ float red[256];

    const int t  = threadIdx.x;
    const int n0 = blockIdx.x * 32;
    if (t < 32) sid[t] = g_idx[n0 + t];
    __syncthreads();

    const int w = t >> 5, lane = t & 31;
#pragma unroll
    for (int r = w * 4; r < w * 4 + 4; ++r) {
        const float* src = emb + (size_t)sid[r] * CDIM;
#pragma unroll
        for (int i = 0; i < CDIM; i += 32) es[r][i + lane] = src[i + lane];
    }
    __syncthreads();

    const int b = n0 >> 10, hwb = n0 & 1023;
    float acc = 0.f;
#pragma unroll 4
    for (int p = 0; p < 32; ++p) {
        int c = p * 8 + (t >> 5);
        int r = t & 31;
        size_t g = (((size_t)(b * CDIM + c)) << 10) + hwb + r;
        float v  = es[r][c];
        float zv = z[g];
        out[g] = v;
        float df = v - zv;
        acc = fmaf(df, df, acc);
    }
    red[t] = acc;
    __syncthreads();
#pragma unroll
    for (int s = 128; s; s >>= 1) {
        if (t < s) red[t] += red[t + s];
        __syncthreads();
    }
    if (!t) g_partials[blockIdx.x] = red[0];
}

// K4: final loss = (1 + BETA) * mean((z_q - z)^2)
__global__ void k_loss(float* __restrict__ lossOut) {
    __shared__ float red[256];
    const int t = threadIdx.x;
    float s = 0.f;
    for (int i = t; i < 2048; i += 256) s += g_partials[i];
    red[t] = s;
    __syncthreads();
#pragma unroll
    for (int st = 128; st; st >>= 1) {
        if (t < st) red[t] += red[t + st];
        __syncthreads();
    }
    if (!t) {
        float m = red[0] * (1.0f / 16777216.0f);
        lossOut[0] = m + 0.25f * m;
    }
}

// ---------------------------------------------------------------------------
extern "C" void kernel_launch(void* const* d_in, const int* in_sizes, int n_in,
                              void* d_out, int out_size) {
    const float* z   = (const float*)d_in[0];
    const float* emb = (const float*)d_in[1];
    float* out       = (float*)d_out;

    cudaFuncSetAttribute(k_dist_argmin,
                         cudaFuncAttributeMaxDynamicSharedMemorySize,
                         F_TOT * 4);

    k_epack<<<1024, 256>>>(emb);
    k_esq<<<(KCODES * 32) / 256, 256>>>(emb);
    k_zsq<<<NROWS / 256, 256>>>(z);
    k_dist_argmin<<<NROWS / 128, 256, F_TOT * 4>>>(z);
    k_output<<<NROWS / 32, 256>>>(z, emb, out);
    k_loss<<<1, 256>>>(out + (size_t)out_size - 1);
}